// round 2
// baseline (speedup 1.0000x reference)
#include <cuda_runtime.h>

typedef unsigned long long u64;

#define TOLF 1e-3f
#define BTOT 4096
#define MAXSTEPS 50
#define KS 68   // Km shared row stride (floats), keeps 16B align + low conflicts
#define VS 36   // vec shared row stride

// Persistent device scratch (no cudaMalloc allowed).
__device__ float g_AF[64 * BTOT];   // [a][b]
__device__ float g_LF[64 * BTOT];   // [l][b]
__device__ float g_AFf[64 * BTOT];
__device__ float g_LFf[64 * BTOT];
__device__ unsigned g_errA[MAXSTEPS];
__device__ unsigned g_errL[MAXSTEPS];

__device__ __forceinline__ u64 pack2(float x, float y) {
    u64 r; asm("mov.b64 %0,{%1,%2};" : "=l"(r) : "f"(x), "f"(y)); return r;
}
__device__ __forceinline__ float2 unpack2(u64 v) {
    float2 r; asm("mov.b64 {%0,%1},%2;" : "=f"(r.x), "=f"(r.y) : "l"(v)); return r;
}
__device__ __forceinline__ u64 ffma2(u64 a, u64 b, u64 c) {
    u64 d; asm("fma.rn.f32x2 %0,%1,%2,%3;" : "=l"(d) : "l"(a), "l"(b), "l"(c)); return d;
}
__device__ __forceinline__ void ld4(const float* __restrict__ p, float r[4]) {
    float4 v = *(const float4*)p;
    r[0] = v.x; r[1] = v.y; r[2] = v.z; r[3] = v.w;
}

__global__ void init_kernel() {
    const int n = 64 * BTOT;
    for (int i = blockIdx.x * blockDim.x + threadIdx.x; i < n;
         i += gridDim.x * blockDim.x) {
        g_AF[i] = 0.f;
        g_LF[i] = 0.f;
    }
    if (blockIdx.x == 0 && threadIdx.x < MAXSTEPS) {
        g_errA[threadIdx.x] = 0u;
        g_errL[threadIdx.x] = 0u;
    }
}

// One dual matvec phase: accL[r][b] = sum_k KmA[k][r]*vA[k][b]
//                        accA[r][b] = sum_k KmL[k][r]*vL[k][b]
__device__ __forceinline__ void mm_phase(
    const float* __restrict__ KmA, const float* __restrict__ KmL,
    const float* __restrict__ vA, const float* __restrict__ vL,
    int rq, int bq, float accL[4][4], float accA[4][4])
{
#pragma unroll
    for (int i = 0; i < 4; i++)
#pragma unroll
        for (int j = 0; j < 4; j++) { accL[i][j] = 0.f; accA[i][j] = 0.f; }
#pragma unroll 4
    for (int k = 0; k < 64; k++) {
        float ka[4], va[4], kl[4], vl[4];
        ld4(KmA + k * KS + rq * 4, ka);
        ld4(vA + k * VS + bq * 4, va);
        ld4(KmL + k * KS + rq * 4, kl);
        ld4(vL + k * VS + bq * 4, vl);
#pragma unroll
        for (int i = 0; i < 4; i++)
#pragma unroll
            for (int j = 0; j < 4; j++) {
                accL[i][j] = fmaf(ka[i], va[j], accL[i][j]);
                accA[i][j] = fmaf(kl[i], vl[j], accA[i][j]);
            }
    }
}

// One Sinkhorn body for 32 batches per block. t = 0-based body index.
// Gating replicates jax.lax.while_loop: body t runs iff t < max_step and
// (t == 0 or err[t-1] >= TOL). isFinal: compute the post-loop step_fn into
// g_AFf/g_LFf unconditionally, no err.
__global__ void __launch_bounds__(128) step_kernel(
    const float* __restrict__ LT, const float* __restrict__ K,
    const float* __restrict__ AT, const int* __restrict__ max_step,
    int t, int isFinal)
{
    if (!isFinal) {
        if (t >= *max_step) return;
        if (t > 0) {
            float ep = __uint_as_float(g_errA[t - 1]) + __uint_as_float(g_errL[t - 1]);
            if (ep < TOLF) return;
        }
    }
    extern __shared__ float sm[];
    float* KmA = sm;                       // [64][KS]: KmA[a][l] = Km[l][a]
    float* KmL = sm + 64 * KS;             // [64][KS]: KmL[l][a] = Km[l][a]
    float* sAF = KmL + 64 * KS;            // [64][VS] k-major vecs
    float* sLF = sAF + 64 * VS;
    float* sLdi = sLF + 64 * VS;
    float* sAdi = sLdi + 64 * VS;
    float* sATm = sAdi + 64 * VS;          // [64]
    __shared__ float redA[4], redL[4];

    const int tid = threadIdx.x;
    const int bq = tid & 7;     // 4 batches each
    const int rq = tid >> 3;    // 4 rows each (0..15)
    const int b0 = blockIdx.x * 32;

    // LT tile for this thread: ltv[i][j] = LT[b0+bq*4+j][rq*4+i]
    float ltv[4][4];
#pragma unroll
    for (int j = 0; j < 4; j++) {
        float col[4];
        ld4(LT + (b0 + bq * 4 + j) * 64 + rq * 4, col);
#pragma unroll
        for (int i = 0; i < 4; i++) ltv[i][j] = col[i];
    }

    for (int i = tid; i < 4096; i += 128) {
        int l = i >> 6, a = i & 63;
        float v = fmaxf(K[i], 0.f);   // _mask == relu in forward
        KmL[l * KS + a] = v;
        KmA[a * KS + l] = v;
    }
    if (tid < 64) sATm[tid] = fmaxf(AT[tid], 0.f);
    for (int i = tid; i < 2048; i += 128) {
        int k = i >> 5, bl = i & 31;
        sAF[k * VS + bl] = g_AF[k * BTOT + b0 + bl];
        sLF[k * VS + bl] = g_LF[k * BTOT + b0 + bl];
    }
    __syncthreads();

    float acc1[4][4], acc2[4][4];

    // Phase A: acc1 = Km@AF (rows l) -> Ldi ; acc2 = Km^T@LF (rows a) -> Adi
    mm_phase(KmA, KmL, sAF, sLF, rq, bq, acc1, acc2);
#pragma unroll
    for (int i = 0; i < 4; i++) {
        int r = rq * 4 + i;
        float at = sATm[r];
#pragma unroll
        for (int j = 0; j < 4; j++) {
            int b = bq * 4 + j;
            sLdi[r * VS + b] = ltv[i][j] / (acc1[i][j] + 1.f);
            sAdi[r * VS + b] = at / (acc2[i][j] + 1.f);
        }
    }
    __syncthreads();

    // Phase B: acc1 = Km@Adi (rows l) -> LF_n ; acc2 = Km^T@Ldi (rows a) -> AF_n
    mm_phase(KmA, KmL, sAdi, sLdi, rq, bq, acc1, acc2);

    float* dstA = isFinal ? g_AFf : g_AF;
    float* dstL = isFinal ? g_LFf : g_LF;
    float eA = 0.f, eL = 0.f;
#pragma unroll
    for (int i = 0; i < 4; i++) {
        int r = rq * 4 + i;
        float at = sATm[r];
        float4 oA, oL;
        float vA[4], vL[4];
#pragma unroll
        for (int j = 0; j < 4; j++) {
            int b = bq * 4 + j;
            float afn = at / (acc2[i][j] + 1.f);
            float lfn = ltv[i][j] / (acc1[i][j] + 1.f);
            if (!isFinal) {
                float ao = sAF[r * VS + b];
                float lo = sLF[r * VS + b];
                eA = fmaxf(eA, fabsf(afn - ao) / (ao + 1e-5f));
                eL = fmaxf(eL, fabsf(lfn - lo) / (lo + 1e-5f));
            }
            vA[j] = afn; vL[j] = lfn;
        }
        oA = make_float4(vA[0], vA[1], vA[2], vA[3]);
        oL = make_float4(vL[0], vL[1], vL[2], vL[3]);
        *(float4*)&dstA[r * BTOT + b0 + bq * 4] = oA;
        *(float4*)&dstL[r * BTOT + b0 + bq * 4] = oL;
    }

    if (!isFinal) {
#pragma unroll
        for (int off = 16; off; off >>= 1) {
            eA = fmaxf(eA, __shfl_xor_sync(0xffffffffu, eA, off));
            eL = fmaxf(eL, __shfl_xor_sync(0xffffffffu, eL, off));
        }
        int wid = tid >> 5;
        if ((tid & 31) == 0) { redA[wid] = eA; redL[wid] = eL; }
        __syncthreads();
        if (tid == 0) {
            float mA = fmaxf(fmaxf(redA[0], redA[1]), fmaxf(redA[2], redA[3]));
            float mL = fmaxf(fmaxf(redL[0], redL[1]), fmaxf(redL[2], redL[3]));
            atomicMax(&g_errA[t], __float_as_uint(mA));
            atomicMax(&g_errL[t], __float_as_uint(mL));
        }
    }
}

// y[b][y] = sum_{la} Km[l][a]*LFf[l][b]*AFf[a][b]*u[la][y] + sum_a AFf[a][b]*e[a][y] + bias[y]
// f32x2-packed over y pairs; coefficients replicated u64. 32 batches/block.
__global__ void __launch_bounds__(128) out_kernel(
    const float* __restrict__ K, const float* __restrict__ u,
    const float* __restrict__ e, const float* __restrict__ bias,
    float* __restrict__ out)
{
    __shared__ float sLFf[64 * 32];
    __shared__ float sAFf[64 * 32];
    __shared__ u64 sCoef[16 * 32];   // [kk][b], both halves identical
    __shared__ u64 sU[16 * 64];      // [kk][yp], native float2 y-pairs

    const int tid = threadIdx.x;
    const int b0 = blockIdx.x * 32;
    const int bq = tid & 7;    // 4 b each
    const int yq = tid >> 3;   // 0..15, 4 y-pairs (8 y) each

    for (int i = tid; i < 2048; i += 128) {
        int k = i >> 5, bl = i & 31;
        sLFf[k * 32 + bl] = g_LFf[k * BTOT + b0 + bl];
        sAFf[k * 32 + bl] = g_AFf[k * BTOT + b0 + bl];
    }
    __syncthreads();

    u64 acc[4][4];
#pragma unroll
    for (int i = 0; i < 4; i++)
#pragma unroll
        for (int j = 0; j < 4; j++) acc[i][j] = 0ull;

    const float2* u2 = (const float2*)u;
    const float2* e2 = (const float2*)e;

    // main contraction over la = 0..4095, then e-term over a = 0..63
    for (int pass = 0; pass < 2; pass++) {
        const int ktot = pass ? 64 : 4096;
        for (int kb = 0; kb < ktot; kb += 16) {
            __syncthreads();
#pragma unroll
            for (int j = 0; j < 4; j++) {
                int idx = tid + j * 128;      // 0..511
                int kk = idx >> 5, bl = idx & 31;
                int k = kb + kk;
                float c;
                if (pass == 0) {
                    float km = fmaxf(K[k], 0.f);   // K linear index == l*64+a
                    c = km * sLFf[(k >> 6) * 32 + bl] * sAFf[(k & 63) * 32 + bl];
                } else {
                    c = sAFf[k * 32 + bl];
                }
                sCoef[kk * 32 + bl] = pack2(c, c);
            }
#pragma unroll
            for (int j = 0; j < 8; j++) {
                int idx = tid + j * 128;      // 0..1023
                int kk = idx >> 6, yp = idx & 63;
                float2 tv = pass == 0 ? u2[(kb + kk) * 64 + yp]
                                      : e2[(kb + kk) * 64 + yp];
                sU[kk * 64 + yp] = pack2(tv.x, tv.y);
            }
            __syncthreads();
#pragma unroll
            for (int kk = 0; kk < 16; kk++) {
                ulonglong2 c01 = *(const ulonglong2*)&sCoef[kk * 32 + bq * 4];
                ulonglong2 c23 = *(const ulonglong2*)&sCoef[kk * 32 + bq * 4 + 2];
                ulonglong2 u01 = *(const ulonglong2*)&sU[kk * 64 + yq * 4];
                ulonglong2 u23 = *(const ulonglong2*)&sU[kk * 64 + yq * 4 + 2];
                u64 cv[4] = {c01.x, c01.y, c23.x, c23.y};
                u64 uv[4] = {u01.x, u01.y, u23.x, u23.y};
#pragma unroll
                for (int i = 0; i < 4; i++)
#pragma unroll
                    for (int j = 0; j < 4; j++)
                        acc[i][j] = ffma2(cv[i], uv[j], acc[i][j]);
            }
        }
    }

    // bias + store
    float bb[8];
    ld4(bias + yq * 8, bb);
    ld4(bias + yq * 8 + 4, bb + 4);
#pragma unroll
    for (int i = 0; i < 4; i++) {
        int b = b0 + bq * 4 + i;
        float2 v0 = unpack2(acc[i][0]);
        float2 v1 = unpack2(acc[i][1]);
        float2 v2 = unpack2(acc[i][2]);
        float2 v3 = unpack2(acc[i][3]);
        float4 o0 = make_float4(v0.x + bb[0], v0.y + bb[1], v1.x + bb[2], v1.y + bb[3]);
        float4 o1 = make_float4(v2.x + bb[4], v2.y + bb[5], v3.x + bb[6], v3.y + bb[7]);
        *(float4*)&out[b * 128 + yq * 8] = o0;
        *(float4*)&out[b * 128 + yq * 8 + 4] = o1;
    }
}

extern "C" void kernel_launch(void* const* d_in, const int* in_sizes, int n_in,
                              void* d_out, int out_size) {
    const float* LT = (const float*)d_in[0];
    const float* K  = (const float*)d_in[1];
    const float* AT = (const float*)d_in[2];
    const float* u  = (const float*)d_in[3];
    const float* e  = (const float*)d_in[4];
    const float* bv = (const float*)d_in[5];
    const int* ms   = (const int*)d_in[6];

    const int shbytes = (64 * KS * 2 + 64 * VS * 4 + 64) * sizeof(float); // 71936
    cudaFuncSetAttribute(step_kernel, cudaFuncAttributeMaxDynamicSharedMemorySize,
                         shbytes);

    init_kernel<<<256, 256>>>();
    for (int t = 0; t < MAXSTEPS; t++)
        step_kernel<<<128, 128, shbytes>>>(LT, K, AT, ms, t, 0);
    step_kernel<<<128, 128, shbytes>>>(LT, K, AT, ms, 0, 1);   // post-loop step_fn
    out_kernel<<<128, 128>>>(K, u, e, bv, (float*)d_out);
}

// round 3
// speedup vs baseline: 1.1487x; 1.1487x over previous
#include <cuda_runtime.h>

typedef unsigned long long u64;

#define TOLF  1e-3f
#define NSTEP 51          // 50 loop bodies + 1 post-loop step_fn
#define SP    18          // u64 stride for state vectors [64][SP]
#define ONE2  0x3F8000003F800000ULL

// Snapshots: g_snap*[i] = state after body (i+1). 2×53.5MB.
__device__ u64 g_snapAF[NSTEP][64][2048];
__device__ u64 g_snapLF[NSTEP][64][2048];
__device__ unsigned g_errA[64];
__device__ unsigned g_errL[64];

__device__ __forceinline__ u64 pack2(float x, float y) {
    u64 r; asm("mov.b64 %0,{%1,%2};" : "=l"(r) : "f"(x), "f"(y)); return r;
}
__device__ __forceinline__ float2 unpack2(u64 v) {
    float2 r; asm("mov.b64 {%0,%1},%2;" : "=f"(r.x), "=f"(r.y) : "l"(v)); return r;
}
__device__ __forceinline__ u64 ffma2(u64 a, u64 b, u64 c) {
    u64 d; asm("fma.rn.f32x2 %0,%1,%2,%3;" : "=l"(d) : "l"(a), "l"(b), "l"(c)); return d;
}
__device__ __forceinline__ u64 fadd2(u64 a, u64 b) {
    u64 d; asm("add.rn.f32x2 %0,%1,%2;" : "=l"(d) : "l"(a), "l"(b)); return d;
}
__device__ __forceinline__ void stcs2(u64* p, u64 a, u64 b) {
    asm volatile("st.global.cs.v2.u64 [%0],{%1,%2};" :: "l"(p), "l"(a), "l"(b));
}

__global__ void init_kernel() {
    if (threadIdx.x < 64) { g_errA[threadIdx.x] = 0u; g_errL[threadIdx.x] = 0u; }
}

// acc[i][j] += sum_k kb[k*68 + r0+i] * vb[k*SP + p0+j]  (km replicated to f32x2)
__device__ __forceinline__ void gemv_phase(const float* __restrict__ kb,
                                           const u64* __restrict__ vb,
                                           int r0, int p0, u64 acc[4][4]) {
#pragma unroll
    for (int i = 0; i < 4; i++)
#pragma unroll
        for (int j = 0; j < 4; j++) acc[i][j] = 0ull;
#pragma unroll 4
    for (int k = 0; k < 64; k++) {
        float4 kv = *(const float4*)(kb + k * 68 + r0);
        ulonglong2 va = *(const ulonglong2*)(vb + k * SP + p0);
        ulonglong2 vc = *(const ulonglong2*)(vb + k * SP + p0 + 2);
        u64 kp[4] = {pack2(kv.x, kv.x), pack2(kv.y, kv.y),
                     pack2(kv.z, kv.z), pack2(kv.w, kv.w)};
        u64 vv[4] = {va.x, va.y, vc.x, vc.y};
#pragma unroll
        for (int i = 0; i < 4; i++)
#pragma unroll
            for (int j = 0; j < 4; j++) acc[i][j] = ffma2(kp[i], vv[j], acc[i][j]);
    }
}

__device__ __forceinline__ u64 div1p(u64 numer, u64 acc) {
    float2 t = unpack2(fadd2(acc, ONE2));
    float2 n = unpack2(numer);
    return pack2(__fdividef(n.x, t.x), __fdividef(n.y, t.y));
}

// Persistent fused Sinkhorn: 51 bodies, 32 batches/block, 128 blocks, 128 thr.
// mv=0 threads own L-rows (use Kml, numer=LT), mv=1 own A-rows (Kma, ATm).
__global__ void __launch_bounds__(128) iter_kernel(const float* __restrict__ LT,
                                                   const float* __restrict__ K,
                                                   const float* __restrict__ AT) {
    extern __shared__ float sm[];
    float* Kma = sm;                    // [l][a], a contiguous (k=l, rows=a)
    float* Kml = sm + 64 * 68;          // [a][l], l contiguous (k=a, rows=l)
    u64* sAF  = (u64*)(sm + 2 * 64 * 68);
    u64* sLF  = sAF + 64 * SP;
    u64* sLdi = sLF + 64 * SP;
    u64* sAdi = sLdi + 64 * SP;
    __shared__ float red[4];

    const int tid = threadIdx.x;
    const int mv = tid >> 6;                 // 0: L-rows, 1: A-rows
    const int r0 = ((tid >> 2) & 15) * 4;
    const int p0 = (tid & 3) * 4;
    const int b0 = blockIdx.x * 32;
    const int bp0 = blockIdx.x * 16;

    for (int i = tid; i < 4096; i += 128) {
        int l = i >> 6, a = i & 63;
        float v = fmaxf(K[i], 0.f);          // _mask == relu (forward)
        Kma[l * 68 + a] = v;
        Kml[a * 68 + l] = v;
    }
    u64 numer[4][4];
    if (mv == 0) {
#pragma unroll
        for (int i = 0; i < 4; i++)
#pragma unroll
            for (int j = 0; j < 4; j++) {
                int pp = p0 + j;
                numer[i][j] = pack2(LT[(b0 + 2 * pp) * 64 + r0 + i],
                                    LT[(b0 + 2 * pp + 1) * 64 + r0 + i]);
            }
    } else {
#pragma unroll
        for (int i = 0; i < 4; i++) {
            float at = fmaxf(AT[r0 + i], 0.f);
            u64 v = pack2(at, at);
#pragma unroll
            for (int j = 0; j < 4; j++) numer[i][j] = v;
        }
    }
    for (int idx = tid; idx < 64 * 16; idx += 128) {
        int k = idx >> 4, pp = idx & 15;
        sAF[k * SP + pp] = 0ull;
        sLF[k * SP + pp] = 0ull;
    }
    __syncthreads();

    const float* kb = (mv == 0) ? Kml : Kma;
    const int wid = tid >> 5;

    for (int it = 0; it < NSTEP; it++) {
        u64 acc[4][4];
        // phase 1: Ldi = LT/(Km@AF+1) ; Adi = ATm/(Km^T@LF+1)
        gemv_phase(kb, (mv == 0) ? sAF : sLF, r0, p0, acc);
        {
            u64* dst = (mv == 0) ? sLdi : sAdi;
#pragma unroll
            for (int i = 0; i < 4; i++)
#pragma unroll
                for (int j = 0; j < 4; j++)
                    dst[(r0 + i) * SP + p0 + j] = div1p(numer[i][j], acc[i][j]);
        }
        __syncthreads();
        // phase 2: LF_n = LT/(Km@Adi+1) ; AF_n = ATm/(Km^T@Ldi+1)
        gemv_phase(kb, (mv == 0) ? sAdi : sLdi, r0, p0, acc);
        {
            u64* st = (mv == 0) ? sLF : sAF;
            u64* gs = (mv == 0) ? &g_snapLF[it][0][0] : &g_snapAF[it][0][0];
            const bool doErr = (it < NSTEP - 1);
            float emax = 0.f;
#pragma unroll
            for (int i = 0; i < 4; i++) {
                int row = r0 + i;
                u64 nr[4];
#pragma unroll
                for (int j = 0; j < 4; j++) {
                    u64 nv = div1p(numer[i][j], acc[i][j]);
                    if (doErr) {
                        float2 o = unpack2(st[row * SP + p0 + j]);
                        float2 n = unpack2(nv);
                        emax = fmaxf(emax, __fdividef(fabsf(n.x - o.x), o.x + 1e-5f));
                        emax = fmaxf(emax, __fdividef(fabsf(n.y - o.y), o.y + 1e-5f));
                    }
                    st[row * SP + p0 + j] = nv;
                    nr[j] = nv;
                }
                u64* gp = gs + row * 2048 + bp0 + p0;
                stcs2(gp, nr[0], nr[1]);
                stcs2(gp + 2, nr[2], nr[3]);
            }
            if (doErr) {
#pragma unroll
                for (int off = 16; off; off >>= 1)
                    emax = fmaxf(emax, __shfl_xor_sync(0xffffffffu, emax, off));
                if ((tid & 31) == 0) red[wid] = emax;
            }
            __syncthreads();
            if (doErr) {
                if (tid == 0)
                    atomicMax(&g_errL[it], __float_as_uint(fmaxf(red[0], red[1])));
                else if (tid == 64)
                    atomicMax(&g_errA[it], __float_as_uint(fmaxf(red[2], red[3])));
            }
        }
    }
}

// y[b][:] = sum_{la} Km[la]*LFf[l][b]*AFf[a][b]*u[la][:] + sum_a AFf[a][b]*e[a][:] + bias
// 32 batches/block. Tile: 8 batches x 4 y-pairs per thread, k split across
// warp halves (combined once at the end via shfl_xor 16).
__global__ void __launch_bounds__(128) out_kernel(const float* __restrict__ K,
                                                  const float* __restrict__ u,
                                                  const float* __restrict__ e,
                                                  const float* __restrict__ bias,
                                                  const int* __restrict__ ms,
                                                  float* __restrict__ out) {
    __shared__ float sLFf[64 * 32];
    __shared__ float sAFf[64 * 32];
    __shared__ float sCoef[16 * 36];
    __shared__ u64 sU[16 * 66];

    // Reference stopping step: N = first body t (1-based) with err_t < TOL, else ms.
    // Final state = state N+1 = snapshot[N].
    const int msc = min(*ms, NSTEP - 1);
    int N = msc;
    for (int t = 0; t < msc; t++) {
        float ev = __uint_as_float(g_errA[t]) + __uint_as_float(g_errL[t]);
        if (ev < TOLF) { N = t + 1; break; }
    }

    const int tid = threadIdx.x;
    const int khalf = (tid & 31) >> 4;
    const int sub = tid & 15;
    const int btile = sub >> 2;                    // batches btile*8 .. +7
    const int yptile = (tid >> 5) * 4 + (sub & 3); // y-pairs yptile*4 .. +3
    const int b0 = blockIdx.x * 32;
    const int bp0 = blockIdx.x * 16;

    for (int idx = tid; idx < 1024; idx += 128) {
        int row = idx >> 4, pp = idx & 15;
        ((u64*)sLFf)[row * 16 + pp] = g_snapLF[N][row][bp0 + pp];
        ((u64*)sAFf)[row * 16 + pp] = g_snapAF[N][row][bp0 + pp];
    }
    __syncthreads();

    u64 acc[8][4];
#pragma unroll
    for (int i = 0; i < 8; i++)
#pragma unroll
        for (int j = 0; j < 4; j++) acc[i][j] = 0ull;

    for (int pass = 0; pass < 2; pass++) {
        const int ktot = pass ? 64 : 4096;
        const float2* W = pass ? (const float2*)e : (const float2*)u;
        for (int kb = 0; kb < ktot; kb += 16) {
            __syncthreads();
            {   // coefficient staging: 4 per thread
                int idx = tid * 4;
                int kk = idx >> 5, bb = idx & 31;
                int k = kb + kk;
                int ai = pass ? k : (k & 63);
                float4 af = *(const float4*)&sAFf[ai * 32 + bb];
                float4 c;
                if (pass == 0) {
                    float km = fmaxf(__ldg(&K[k]), 0.f);
                    float4 lf = *(const float4*)&sLFf[(k >> 6) * 32 + bb];
                    c = make_float4(km * lf.x * af.x, km * lf.y * af.y,
                                    km * lf.z * af.z, km * lf.w * af.w);
                } else {
                    c = af;
                }
                *(float4*)&sCoef[kk * 36 + bb] = c;
            }
#pragma unroll
            for (int j = 0; j < 8; j++) {  // u staging: 8 per thread, coalesced
                int idx = tid + j * 128;
                int kk = idx >> 6, yp = idx & 63;
                float2 w = W[(kb + kk) * 64 + yp];
                sU[kk * 66 + yp] = pack2(w.x, w.y);
            }
            __syncthreads();
#pragma unroll
            for (int kkk = 0; kkk < 8; kkk++) {
                int kk = khalf * 8 + kkk;
                float4 c0 = *(const float4*)&sCoef[kk * 36 + btile * 8];
                float4 c1 = *(const float4*)&sCoef[kk * 36 + btile * 8 + 4];
                ulonglong2 u01 = *(const ulonglong2*)&sU[kk * 66 + yptile * 4];
                ulonglong2 u23 = *(const ulonglong2*)&sU[kk * 66 + yptile * 4 + 2];
                u64 uv[4] = {u01.x, u01.y, u23.x, u23.y};
                u64 cp[8] = {pack2(c0.x, c0.x), pack2(c0.y, c0.y),
                             pack2(c0.z, c0.z), pack2(c0.w, c0.w),
                             pack2(c1.x, c1.x), pack2(c1.y, c1.y),
                             pack2(c1.z, c1.z), pack2(c1.w, c1.w)};
#pragma unroll
                for (int i = 0; i < 8; i++)
#pragma unroll
                    for (int j = 0; j < 4; j++)
                        acc[i][j] = ffma2(cp[i], uv[j], acc[i][j]);
            }
        }
    }

    // combine k-halves (lane ^ 16 holds the partner partial sums)
#pragma unroll
    for (int i = 0; i < 8; i++)
#pragma unroll
        for (int j = 0; j < 4; j++) {
            u64 o = __shfl_xor_sync(0xffffffffu, acc[i][j], 16);
            acc[i][j] = fadd2(acc[i][j], o);
        }

    float bb8[8];
    {
        float4 t0 = *(const float4*)(bias + yptile * 8);
        float4 t1 = *(const float4*)(bias + yptile * 8 + 4);
        bb8[0]=t0.x; bb8[1]=t0.y; bb8[2]=t0.z; bb8[3]=t0.w;
        bb8[4]=t1.x; bb8[5]=t1.y; bb8[6]=t1.z; bb8[7]=t1.w;
    }
#pragma unroll
    for (int bi = 0; bi < 4; bi++) {
        int lb = khalf * 4 + bi;
        int b = b0 + btile * 8 + lb;
        float2 v0 = unpack2(acc[lb][0]);
        float2 v1 = unpack2(acc[lb][1]);
        float2 v2 = unpack2(acc[lb][2]);
        float2 v3 = unpack2(acc[lb][3]);
        float4 o0 = make_float4(v0.x + bb8[0], v0.y + bb8[1],
                                v1.x + bb8[2], v1.y + bb8[3]);
        float4 o1 = make_float4(v2.x + bb8[4], v2.y + bb8[5],
                                v3.x + bb8[6], v3.y + bb8[7]);
        *(float4*)&out[b * 128 + yptile * 8] = o0;
        *(float4*)&out[b * 128 + yptile * 8 + 4] = o1;
    }
}

extern "C" void kernel_launch(void* const* d_in, const int* in_sizes, int n_in,
                              void* d_out, int out_size) {
    const float* LT = (const float*)d_in[0];
    const float* K  = (const float*)d_in[1];
    const float* AT = (const float*)d_in[2];
    const float* u  = (const float*)d_in[3];
    const float* e  = (const float*)d_in[4];
    const float* bv = (const float*)d_in[5];
    const int* ms   = (const int*)d_in[6];

    const int shbytes = (2 * 64 * 68) * 4 + (4 * 64 * SP) * 8;  // 71680
    cudaFuncSetAttribute(iter_kernel, cudaFuncAttributeMaxDynamicSharedMemorySize,
                         shbytes);

    init_kernel<<<1, 64>>>();
    iter_kernel<<<128, 128, shbytes>>>(LT, K, AT);
    out_kernel<<<128, 128>>>(K, u, e, bv, ms, (float*)d_out);
}

// round 4
// speedup vs baseline: 1.9709x; 1.7157x over previous
#include <cuda_runtime.h>

typedef unsigned long long u64;

#define TOLF  1e-3f
#define NSTEP 51          // 50 loop bodies + 1 post-loop step_fn
#define CHUNK 4
#define SP    18          // u64 stride for state vectors [64][SP]
#define ONE2  0x3F8000003F800000ULL

// Snapshots: g_snap*[it] = state after body it+1 (i.e. state_{it+1}).
__device__ u64 g_snapAF[NSTEP][64][2048];
__device__ u64 g_snapLF[NSTEP][64][2048];
__device__ unsigned g_errA[64];
__device__ unsigned g_errL[64];

__device__ __forceinline__ u64 pack2(float x, float y) {
    u64 r; asm("mov.b64 %0,{%1,%2};" : "=l"(r) : "f"(x), "f"(y)); return r;
}
__device__ __forceinline__ float2 unpack2(u64 v) {
    float2 r; asm("mov.b64 {%0,%1},%2;" : "=f"(r.x), "=f"(r.y) : "l"(v)); return r;
}
__device__ __forceinline__ u64 ffma2(u64 a, u64 b, u64 c) {
    u64 d; asm("fma.rn.f32x2 %0,%1,%2,%3;" : "=l"(d) : "l"(a), "l"(b), "l"(c)); return d;
}
__device__ __forceinline__ u64 fadd2(u64 a, u64 b) {
    u64 d; asm("add.rn.f32x2 %0,%1,%2;" : "=l"(d) : "l"(a), "l"(b)); return d;
}
__device__ __forceinline__ void stcs2(u64* p, u64 a, u64 b) {
    asm volatile("st.global.cs.v2.u64 [%0],{%1,%2};" :: "l"(p), "l"(a), "l"(b));
}
__device__ __forceinline__ u64 div1p(u64 numer, u64 acc) {
    float2 t = unpack2(fadd2(acc, ONE2));
    float2 n = unpack2(numer);
    return pack2(__fdividef(n.x, t.x), __fdividef(n.y, t.y));
}

__global__ void init_kernel() {
    if (threadIdx.x < 64) { g_errA[threadIdx.x] = 0u; g_errL[threadIdx.x] = 0u; }
}

// acc[i][j] += sum_k kb[k*68 + r0+i] * vb[k*SP + p0+j]   (2 rows x 4 pairs)
__device__ __forceinline__ void gemv2(const float* __restrict__ kb,
                                      const u64* __restrict__ vb,
                                      int r0, int p0, u64 acc[2][4]) {
#pragma unroll
    for (int i = 0; i < 2; i++)
#pragma unroll
        for (int j = 0; j < 4; j++) acc[i][j] = 0ull;
#pragma unroll 8
    for (int k = 0; k < 64; k++) {
        float2 kv = *(const float2*)(kb + k * 68 + r0);
        ulonglong2 va = *(const ulonglong2*)(vb + k * SP + p0);
        ulonglong2 vc = *(const ulonglong2*)(vb + k * SP + p0 + 2);
        u64 kp0 = pack2(kv.x, kv.x);
        u64 kp1 = pack2(kv.y, kv.y);
        u64 vv[4] = {va.x, va.y, vc.x, vc.y};
#pragma unroll
        for (int j = 0; j < 4; j++) {
            acc[0][j] = ffma2(kp0, vv[j], acc[0][j]);
            acc[1][j] = ffma2(kp1, vv[j], acc[1][j]);
        }
    }
}

// One chunk of CHUNK Sinkhorn bodies [t0, t0+CHUNK). 32 batches/block,
// 128 blocks, 256 threads. mv=0 warps own L-rows, mv=1 own A-rows.
// Gate replicates the while_loop: chunk runs iff t0 <= ms and no body
// t <= t0-2 had err < TOL (the body right after the triggering one must
// still run: it is the reference's post-loop step_fn).
__global__ void __launch_bounds__(256) iter_chunk(const float* __restrict__ LT,
                                                  const float* __restrict__ K,
                                                  const float* __restrict__ AT,
                                                  const int* __restrict__ ms,
                                                  int t0) {
    const int tid = threadIdx.x;
    const int msval = *ms;
    if (t0 > msval) return;
    if (t0 > 0) {
        int conv = 0;
        if (tid <= t0 - 2) {
            float ev = __uint_as_float(g_errA[tid]) + __uint_as_float(g_errL[tid]);
            conv = (ev < TOLF);
        }
        if (__syncthreads_or(conv)) return;
    }

    extern __shared__ float sm[];
    float* Kma = sm;                    // [l][a] (k=l, rows=a)
    float* Kml = sm + 64 * 68;          // [a][l] (k=a, rows=l)
    u64* sAF  = (u64*)(sm + 2 * 64 * 68);
    u64* sLF  = sAF + 64 * SP;
    u64* sLdi = sLF + 64 * SP;
    u64* sAdi = sLdi + 64 * SP;
    __shared__ float red[8];

    const int mv = tid >> 7;                 // 0: L-rows, 1: A-rows
    const int r0 = ((tid >> 2) & 31) * 2;
    const int p0 = (tid & 3) * 4;
    const int b0 = blockIdx.x * 32;
    const int bp0 = blockIdx.x * 16;
    const int wid = tid >> 5;

    for (int i = tid; i < 4096; i += 256) {
        int l = i >> 6, a = i & 63;
        float v = fmaxf(K[i], 0.f);          // _mask == relu (forward)
        Kma[l * 68 + a] = v;
        Kml[a * 68 + l] = v;
    }
    u64 numer[2][4];
    if (mv == 0) {
#pragma unroll
        for (int i = 0; i < 2; i++)
#pragma unroll
            for (int j = 0; j < 4; j++) {
                int pp = p0 + j;
                numer[i][j] = pack2(LT[(b0 + 2 * pp) * 64 + r0 + i],
                                    LT[(b0 + 2 * pp + 1) * 64 + r0 + i]);
            }
    } else {
#pragma unroll
        for (int i = 0; i < 2; i++) {
            float at = fmaxf(AT[r0 + i], 0.f);
            u64 v = pack2(at, at);
#pragma unroll
            for (int j = 0; j < 4; j++) numer[i][j] = v;
        }
    }
    // state: zeros at t0==0 else snapshot[t0-1]
    if (t0 == 0) {
        for (int idx = tid; idx < 64 * 16; idx += 256) {
            int k = idx >> 4, pp = idx & 15;
            sAF[k * SP + pp] = 0ull;
            sLF[k * SP + pp] = 0ull;
        }
    } else {
        for (int idx = tid; idx < 64 * 16; idx += 256) {
            int k = idx >> 4, pp = idx & 15;
            sAF[k * SP + pp] = g_snapAF[t0 - 1][k][bp0 + pp];
            sLF[k * SP + pp] = g_snapLF[t0 - 1][k][bp0 + pp];
        }
    }
    __syncthreads();

    const float* kb = (mv == 0) ? Kml : Kma;
    const int itEnd = min(t0 + CHUNK, NSTEP);

    for (int it = t0; it < itEnd; it++) {
        if (it > msval) break;
        u64 acc[2][4];
        // phase 1: Ldi = LT/(Km@AF+1) ; Adi = ATm/(Km^T@LF+1)
        gemv2(kb, (mv == 0) ? sAF : sLF, r0, p0, acc);
        {
            u64* dst = (mv == 0) ? sLdi : sAdi;
#pragma unroll
            for (int i = 0; i < 2; i++)
#pragma unroll
                for (int j = 0; j < 4; j++)
                    dst[(r0 + i) * SP + p0 + j] = div1p(numer[i][j], acc[i][j]);
        }
        __syncthreads();
        // phase 2: LF_n = LT/(Km@Adi+1) ; AF_n = ATm/(Km^T@Ldi+1)
        gemv2(kb, (mv == 0) ? sAdi : sLdi, r0, p0, acc);
        {
            u64* st = (mv == 0) ? sLF : sAF;
            u64* gs = (mv == 0) ? &g_snapLF[it][0][0] : &g_snapAF[it][0][0];
            float emax = 0.f;
#pragma unroll
            for (int i = 0; i < 2; i++) {
                int row = r0 + i;
                u64 nr[4];
#pragma unroll
                for (int j = 0; j < 4; j++) {
                    u64 nv = div1p(numer[i][j], acc[i][j]);
                    float2 o = unpack2(st[row * SP + p0 + j]);
                    float2 n = unpack2(nv);
                    emax = fmaxf(emax, __fdividef(fabsf(n.x - o.x), o.x + 1e-5f));
                    emax = fmaxf(emax, __fdividef(fabsf(n.y - o.y), o.y + 1e-5f));
                    st[row * SP + p0 + j] = nv;
                    nr[j] = nv;
                }
                u64* gp = gs + row * 2048 + bp0 + p0;
                stcs2(gp, nr[0], nr[1]);
                stcs2(gp + 2, nr[2], nr[3]);
            }
#pragma unroll
            for (int off = 16; off; off >>= 1)
                emax = fmaxf(emax, __shfl_xor_sync(0xffffffffu, emax, off));
            if ((tid & 31) == 0) red[wid] = emax;
            __syncthreads();
            if (tid == 0) {
                float m = fmaxf(fmaxf(red[0], red[1]), fmaxf(red[2], red[3]));
                atomicMax(&g_errL[it], __float_as_uint(m));
            } else if (tid == 128) {
                float m = fmaxf(fmaxf(red[4], red[5]), fmaxf(red[6], red[7]));
                atomicMax(&g_errA[it], __float_as_uint(m));
            }
        }
    }
}

// y[b][:] = sum_{la} Km[la]*LFf[l][b]*AFf[a][b]*u[la][:] + sum_a AFf[a][b]*e[a][:] + bias
// 32 batches/block, 256 threads: each thread 4 batches x 4 y-pairs,
// k split across warp halves (combined via shfl_xor 16).
__global__ void __launch_bounds__(256) out_kernel(const float* __restrict__ K,
                                                  const float* __restrict__ u,
                                                  const float* __restrict__ e,
                                                  const float* __restrict__ bias,
                                                  const int* __restrict__ ms,
                                                  float* __restrict__ out) {
    __shared__ float sLFf[64 * 32];
    __shared__ float sAFf[64 * 32];
    __shared__ float sCoef[16 * 36];
    __shared__ u64 sU[16 * 66];

    // Reference stopping step: N = (first body t with err_t < TOL)+1, else ms.
    // Final state (post-loop step_fn applied) = snapshot[N].
    const int msc = min(*ms, NSTEP - 1);
    int N = msc;
    for (int t = 0; t < msc; t++) {
        float ev = __uint_as_float(g_errA[t]) + __uint_as_float(g_errL[t]);
        if (ev < TOLF) { N = t + 1; break; }
    }

    const int tid = threadIdx.x;
    const int lane = tid & 31;
    const int wid = tid >> 5;
    const int khalf = lane >> 4;
    const int idx128 = wid * 16 + (lane & 15);
    const int bg = idx128 & 7;        // batches bg*4 .. +3
    const int ypg = idx128 >> 3;      // y-pairs ypg*4 .. +3
    const int b0 = blockIdx.x * 32;
    const int bp0 = blockIdx.x * 16;

    for (int idx = tid; idx < 1024; idx += 256) {
        int row = idx >> 4, pp = idx & 15;
        ((u64*)sLFf)[row * 16 + pp] = g_snapLF[N][row][bp0 + pp];
        ((u64*)sAFf)[row * 16 + pp] = g_snapAF[N][row][bp0 + pp];
    }
    __syncthreads();

    u64 acc[4][4];
#pragma unroll
    for (int i = 0; i < 4; i++)
#pragma unroll
        for (int j = 0; j < 4; j++) acc[i][j] = 0ull;

    for (int pass = 0; pass < 2; pass++) {
        const int ktot = pass ? 64 : 4096;
        const float2* W = pass ? (const float2*)e : (const float2*)u;
        for (int kb = 0; kb < ktot; kb += 16) {
            __syncthreads();
            {   // coefficient staging: 2 per thread (512 total)
                int idx = tid * 2;
                int kk = idx >> 5, bb = idx & 31;
                int k = kb + kk;
                int ai = pass ? k : (k & 63);
                float2 af = *(const float2*)&sAFf[ai * 32 + bb];
                float2 c;
                if (pass == 0) {
                    float km = fmaxf(__ldg(&K[k]), 0.f);
                    float2 lf = *(const float2*)&sLFf[(k >> 6) * 32 + bb];
                    c = make_float2(km * lf.x * af.x, km * lf.y * af.y);
                } else {
                    c = af;
                }
                *(float2*)&sCoef[kk * 36 + bb] = c;
            }
#pragma unroll
            for (int j = 0; j < 4; j++) {  // u staging: 4 per thread (1024)
                int idx = tid + j * 256;
                int kk = idx >> 6, yp = idx & 63;
                float2 w = W[(kb + kk) * 64 + yp];
                sU[kk * 66 + yp] = pack2(w.x, w.y);
            }
            __syncthreads();
#pragma unroll
            for (int kkk = 0; kkk < 8; kkk++) {
                int kk = khalf * 8 + kkk;
                float4 c4 = *(const float4*)&sCoef[kk * 36 + bg * 4];
                ulonglong2 u01 = *(const ulonglong2*)&sU[kk * 66 + ypg * 4];
                ulonglong2 u23 = *(const ulonglong2*)&sU[kk * 66 + ypg * 4 + 2];
                u64 uv[4] = {u01.x, u01.y, u23.x, u23.y};
                u64 cp[4] = {pack2(c4.x, c4.x), pack2(c4.y, c4.y),
                             pack2(c4.z, c4.z), pack2(c4.w, c4.w)};
#pragma unroll
                for (int i = 0; i < 4; i++)
#pragma unroll
                    for (int j = 0; j < 4; j++)
                        acc[i][j] = ffma2(cp[i], uv[j], acc[i][j]);
            }
        }
    }

    // combine k-halves (lane ^ 16 holds partner partials)
#pragma unroll
    for (int i = 0; i < 4; i++)
#pragma unroll
        for (int j = 0; j < 4; j++) {
            u64 o = __shfl_xor_sync(0xffffffffu, acc[i][j], 16);
            acc[i][j] = fadd2(acc[i][j], o);
        }

    if (khalf == 0) {
        float bb8[8];
        float4 t0v = *(const float4*)(bias + ypg * 8);
        float4 t1v = *(const float4*)(bias + ypg * 8 + 4);
        bb8[0]=t0v.x; bb8[1]=t0v.y; bb8[2]=t0v.z; bb8[3]=t0v.w;
        bb8[4]=t1v.x; bb8[5]=t1v.y; bb8[6]=t1v.z; bb8[7]=t1v.w;
#pragma unroll
        for (int i = 0; i < 4; i++) {
            int b = b0 + bg * 4 + i;
            float2 v0 = unpack2(acc[i][0]);
            float2 v1 = unpack2(acc[i][1]);
            float2 v2 = unpack2(acc[i][2]);
            float2 v3 = unpack2(acc[i][3]);
            float4 o0 = make_float4(v0.x + bb8[0], v0.y + bb8[1],
                                    v1.x + bb8[2], v1.y + bb8[3]);
            float4 o1 = make_float4(v2.x + bb8[4], v2.y + bb8[5],
                                    v3.x + bb8[6], v3.y + bb8[7]);
            *(float4*)&out[b * 128 + ypg * 8] = o0;
            *(float4*)&out[b * 128 + ypg * 8 + 4] = o1;
        }
    }
}

extern "C" void kernel_launch(void* const* d_in, const int* in_sizes, int n_in,
                              void* d_out, int out_size) {
    const float* LT = (const float*)d_in[0];
    const float* K  = (const float*)d_in[1];
    const float* AT = (const float*)d_in[2];
    const float* u  = (const float*)d_in[3];
    const float* e  = (const float*)d_in[4];
    const float* bv = (const float*)d_in[5];
    const int* ms   = (const int*)d_in[6];

    const int shbytes = (2 * 64 * 68) * 4 + (4 * 64 * SP) * 8;  // 71680
    cudaFuncSetAttribute(iter_chunk, cudaFuncAttributeMaxDynamicSharedMemorySize,
                         shbytes);

    init_kernel<<<1, 64>>>();
    for (int t0 = 0; t0 < NSTEP; t0 += CHUNK)
        iter_chunk<<<128, 256, shbytes>>>(LT, K, AT, ms, t0);
    out_kernel<<<128, 256>>>(K, u, e, bv, ms, (float*)d_out);
}

// round 5
// speedup vs baseline: 2.0885x; 1.0597x over previous
#include <cuda_runtime.h>

typedef unsigned long long u64;

#define TOLF  1e-3f
#define NSTEP 51          // 50 loop bodies + 1 post-loop step_fn
#define CHUNK 6
#define ONE2  0x3F8000003F800000ULL

// Snapshots: g_snap*[it] = state after body it (i.e. state_{it+1}).
__device__ u64 g_snapAF[NSTEP][64][2048];
__device__ u64 g_snapLF[NSTEP][64][2048];
__device__ unsigned g_errA[64];
__device__ unsigned g_errL[64];

__device__ __forceinline__ u64 pack2(float x, float y) {
    u64 r; asm("mov.b64 %0,{%1,%2};" : "=l"(r) : "f"(x), "f"(y)); return r;
}
__device__ __forceinline__ float2 unpack2(u64 v) {
    float2 r; asm("mov.b64 {%0,%1},%2;" : "=f"(r.x), "=f"(r.y) : "l"(v)); return r;
}
__device__ __forceinline__ u64 ffma2(u64 a, u64 b, u64 c) {
    u64 d; asm("fma.rn.f32x2 %0,%1,%2,%3;" : "=l"(d) : "l"(a), "l"(b), "l"(c)); return d;
}
__device__ __forceinline__ u64 fadd2(u64 a, u64 b) {
    u64 d; asm("add.rn.f32x2 %0,%1,%2;" : "=l"(d) : "l"(a), "l"(b)); return d;
}
__device__ __forceinline__ void stcs2(u64* p, u64 a, u64 b) {
    asm volatile("st.global.cs.v2.u64 [%0],{%1,%2};" :: "l"(p), "l"(a), "l"(b));
}
__device__ __forceinline__ u64 div1p(u64 numer, u64 acc) {
    float2 t = unpack2(fadd2(acc, ONE2));
    float2 n = unpack2(numer);
    return pack2(__fdividef(n.x, t.x), __fdividef(n.y, t.y));
}

// Padded smem indexers: the second k-half gets a bank offset so the two
// khalves in a warp never collide (raw khalf delta is always 0 mod 32 banks).
#define VROW 18                                       // u64 stride (16 pairs + 2)
#define VHALF (32 * VROW + 2)                         // +2 u64 = +4 banks
__device__ __forceinline__ int vIdx(int k) { return k * VROW + ((k >> 5) << 1); }
#define KROW 72                                       // float stride
#define KHALF (32 * KROW + 8)                         // +8 floats = +8 banks
__device__ __forceinline__ int kIdx(int k) { return k * KROW + ((k >> 5) << 3); }
#define VBYTES ((64 * VROW + 2) * 8)                  // 9232
#define KBYTES ((64 * KROW + 8) * 4)                  // 18464
#define SHBYTES (2 * KBYTES + 4 * VBYTES)             // 73856

__global__ void init_kernel() {
    if (threadIdx.x < 64) { g_errA[threadIdx.x] = 0u; g_errL[threadIdx.x] = 0u; }
}

// One chunk of CHUNK Sinkhorn bodies [t0, t0+CHUNK). 32 batches/block,
// 128 blocks, 512 threads (16 warps = 4/SMSP). Each thread: 2 rows x 4
// batch-pairs over HALF of k; khalf partials combined via shfl_xor(16);
// thread then owns 1 row x 4 pairs for divide/store/err.
// Gate replicates the while_loop: chunk runs iff t0 <= ms and no body
// t <= t0-2 had err < TOL (the body after the triggering one still runs:
// it is the reference's post-loop step_fn).
__global__ void __launch_bounds__(512) iter_chunk(const float* __restrict__ LT,
                                                  const float* __restrict__ K,
                                                  const float* __restrict__ AT,
                                                  const int* __restrict__ ms,
                                                  int t0) {
    const int tid = threadIdx.x;
    const int msval = *ms;
    if (t0 > msval) return;
    if (t0 > 0) {
        int conv = 0;
        if (tid <= t0 - 2) {
            float ev = __uint_as_float(g_errA[tid]) + __uint_as_float(g_errL[tid]);
            conv = (ev < TOLF);
        }
        if (__syncthreads_or(conv)) return;
    }

    extern __shared__ float sm[];
    float* Kma = sm;                                  // k=l rows, a contiguous
    float* Kml = sm + KBYTES / 4;                     // k=a rows, l contiguous
    u64* sAF  = (u64*)(sm + 2 * (KBYTES / 4));
    u64* sLF  = sAF + VBYTES / 8;
    u64* sLdi = sLF + VBYTES / 8;
    u64* sAdi = sLdi + VBYTES / 8;
    __shared__ float red[16];

    const int w = tid >> 5;
    const int lane = tid & 31;
    const int mv = w >> 3;                // 0: L-rows, 1: A-rows
    const int wg = w & 7;
    const int khalf = lane >> 4;
    const int rgl = (lane >> 2) & 3;
    const int pq = lane & 3;
    const int r0 = wg * 8 + rgl * 2;      // 2 rows r0, r0+1
    const int ro = r0 + khalf;            // owned row for divide/store
    const int p0 = pq * 4;                // 4 batch-pairs
    const int b0 = blockIdx.x * 32;
    const int bp0 = blockIdx.x * 16;

    for (int i = tid; i < 4096; i += 512) {
        int l = i >> 6, a = i & 63;
        float v = fmaxf(K[i], 0.f);       // _mask == relu (forward)
        Kma[kIdx(l) + a] = v;
        Kml[kIdx(a) + l] = v;
    }
    // numer for the OWNED row only (post-combine divide responsibility)
    u64 nmr[4];
    if (mv == 0) {
#pragma unroll
        for (int j = 0; j < 4; j++) {
            int pp = p0 + j;
            nmr[j] = pack2(LT[(b0 + 2 * pp) * 64 + ro],
                           LT[(b0 + 2 * pp + 1) * 64 + ro]);
        }
    } else {
        float at = fmaxf(AT[ro], 0.f);
        u64 v = pack2(at, at);
#pragma unroll
        for (int j = 0; j < 4; j++) nmr[j] = v;
    }
    // state: zeros at t0==0 else snapshot[t0-1]
    for (int idx = tid; idx < 1024; idx += 512) {
        int row = idx >> 4, pp = idx & 15;
        u64 a0 = 0ull, l0 = 0ull;
        if (t0 > 0) {
            a0 = g_snapAF[t0 - 1][row][bp0 + pp];
            l0 = g_snapLF[t0 - 1][row][bp0 + pp];
        }
        sAF[vIdx(row) + pp] = a0;
        sLF[vIdx(row) + pp] = l0;
    }
    __syncthreads();

    const float* kb = ((mv == 0) ? Kml : Kma) + khalf * KHALF + r0;
    const int vhoff = khalf * VHALF + p0;
    const int itEnd = min(t0 + CHUNK, NSTEP);

    for (int it = t0; it < itEnd; it++) {
        if (it > msval) break;
#pragma unroll
        for (int ph = 0; ph < 2; ph++) {
            // ph0: Ldi = LT/(Km@AF+1), Adi = ATm/(Km^T@LF+1)
            // ph1: LF  = LT/(Km@Adi+1), AF  = ATm/(Km^T@Ldi+1)
            const u64* vb = (mv == 0) ? (ph ? sAdi : sAF) : (ph ? sLdi : sLF);
            vb += vhoff;
            u64 acc[2][4];
#pragma unroll
            for (int i = 0; i < 2; i++)
#pragma unroll
                for (int j = 0; j < 4; j++) acc[i][j] = 0ull;
#pragma unroll 8
            for (int kk = 0; kk < 32; kk++) {
                float2 kv = *(const float2*)(kb + kk * KROW);
                ulonglong2 va = *(const ulonglong2*)(vb + kk * VROW);
                ulonglong2 vc = *(const ulonglong2*)(vb + kk * VROW + 2);
                u64 kp0 = pack2(kv.x, kv.x);
                u64 kp1 = pack2(kv.y, kv.y);
                u64 vv[4] = {va.x, va.y, vc.x, vc.y};
#pragma unroll
                for (int j = 0; j < 4; j++) {
                    acc[0][j] = ffma2(kp0, vv[j], acc[0][j]);
                    acc[1][j] = ffma2(kp1, vv[j], acc[1][j]);
                }
            }
            // combine khalf partials: I own row (r0+khalf) = acc[khalf];
            // send the row my partner owns, receive my row's other half.
            u64 res[4];
#pragma unroll
            for (int j = 0; j < 4; j++) {
                u64 send = khalf ? acc[0][j] : acc[1][j];
                u64 recv = __shfl_xor_sync(0xffffffffu, send, 16);
                res[j] = div1p(nmr[j], fadd2(acc[khalf][j], recv));
            }
            if (ph == 0) {
                u64* dst = ((mv == 0) ? sLdi : sAdi) + vIdx(ro) + p0;
                *(ulonglong2*)dst = make_ulonglong2(res[0], res[1]);
                *(ulonglong2*)(dst + 2) = make_ulonglong2(res[2], res[3]);
            } else {
                u64* st = ((mv == 0) ? sLF : sAF) + vIdx(ro) + p0;
                float emax = 0.f;
#pragma unroll
                for (int j = 0; j < 4; j++) {
                    float2 o = unpack2(st[j]);
                    float2 n = unpack2(res[j]);
                    emax = fmaxf(emax, __fdividef(fabsf(n.x - o.x), o.x + 1e-5f));
                    emax = fmaxf(emax, __fdividef(fabsf(n.y - o.y), o.y + 1e-5f));
                    st[j] = res[j];
                }
                u64* gp = ((mv == 0) ? &g_snapLF[it][0][0] : &g_snapAF[it][0][0])
                          + ro * 2048 + bp0 + p0;
                stcs2(gp, res[0], res[1]);
                stcs2(gp + 2, res[2], res[3]);
#pragma unroll
                for (int off = 16; off; off >>= 1)
                    emax = fmaxf(emax, __shfl_xor_sync(0xffffffffu, emax, off));
                if (lane == 0) red[w] = emax;
            }
            __syncthreads();
        }
        // fold per-warp errs (red[] written under ph==1 before the barrier)
        if (tid == 0) {
            float m = red[0];
#pragma unroll
            for (int i = 1; i < 8; i++) m = fmaxf(m, red[i]);
            atomicMax(&g_errL[it], __float_as_uint(m));
        } else if (tid == 256) {
            float m = red[8];
#pragma unroll
            for (int i = 9; i < 16; i++) m = fmaxf(m, red[i]);
            atomicMax(&g_errA[it], __float_as_uint(m));
        }
    }
}

// y[b][:] = sum_{la} Km[la]*LFf[l][b]*AFf[a][b]*u[la][:] + sum_a AFf[a][b]*e[a][:] + bias
// 32 batches/block, 256 threads: each thread 4 batches x 4 y-pairs,
// k split across warp halves (combined via shfl_xor 16).
__global__ void __launch_bounds__(256) out_kernel(const float* __restrict__ K,
                                                  const float* __restrict__ u,
                                                  const float* __restrict__ e,
                                                  const float* __restrict__ bias,
                                                  const int* __restrict__ ms,
                                                  float* __restrict__ out) {
    __shared__ float sLFf[64 * 32];
    __shared__ float sAFf[64 * 32];
    __shared__ float sCoef[16 * 36];
    __shared__ u64 sU[16 * 66];

    // Reference stopping step: N = (first body t with err_t < TOL)+1, else ms.
    // Final state (post-loop step_fn applied) = snapshot[N].
    const int msc = min(*ms, NSTEP - 1);
    int N = msc;
    for (int t = 0; t < msc; t++) {
        float ev = __uint_as_float(g_errA[t]) + __uint_as_float(g_errL[t]);
        if (ev < TOLF) { N = t + 1; break; }
    }

    const int tid = threadIdx.x;
    const int lane = tid & 31;
    const int wid = tid >> 5;
    const int khalf = lane >> 4;
    const int idx128 = wid * 16 + (lane & 15);
    const int bg = idx128 & 7;        // batches bg*4 .. +3
    const int ypg = idx128 >> 3;      // y-pairs ypg*4 .. +3
    const int b0 = blockIdx.x * 32;
    const int bp0 = blockIdx.x * 16;

    for (int idx = tid; idx < 1024; idx += 256) {
        int row = idx >> 4, pp = idx & 15;
        ((u64*)sLFf)[row * 16 + pp] = g_snapLF[N][row][bp0 + pp];
        ((u64*)sAFf)[row * 16 + pp] = g_snapAF[N][row][bp0 + pp];
    }
    __syncthreads();

    u64 acc[4][4];
#pragma unroll
    for (int i = 0; i < 4; i++)
#pragma unroll
        for (int j = 0; j < 4; j++) acc[i][j] = 0ull;

    for (int pass = 0; pass < 2; pass++) {
        const int ktot = pass ? 64 : 4096;
        const float2* W = pass ? (const float2*)e : (const float2*)u;
        for (int kb = 0; kb < ktot; kb += 16) {
            __syncthreads();
            {   // coefficient staging: 2 per thread (512 total)
                int idx = tid * 2;
                int kk = idx >> 5, bb = idx & 31;
                int k = kb + kk;
                int ai = pass ? k : (k & 63);
                float2 af = *(const float2*)&sAFf[ai * 32 + bb];
                float2 c;
                if (pass == 0) {
                    float km = fmaxf(__ldg(&K[k]), 0.f);
                    float2 lf = *(const float2*)&sLFf[(k >> 6) * 32 + bb];
                    c = make_float2(km * lf.x * af.x, km * lf.y * af.y);
                } else {
                    c = af;
                }
                *(float2*)&sCoef[kk * 36 + bb] = c;
            }
#pragma unroll
            for (int j = 0; j < 4; j++) {  // u staging: 4 per thread (1024)
                int idx = tid + j * 256;
                int kk = idx >> 6, yp = idx & 63;
                float2 w = W[(kb + kk) * 64 + yp];
                sU[kk * 66 + yp] = pack2(w.x, w.y);
            }
            __syncthreads();
#pragma unroll
            for (int kkk = 0; kkk < 8; kkk++) {
                int kk = khalf * 8 + kkk;
                float4 c4 = *(const float4*)&sCoef[kk * 36 + bg * 4];
                ulonglong2 u01 = *(const ulonglong2*)&sU[kk * 66 + ypg * 4];
                ulonglong2 u23 = *(const ulonglong2*)&sU[kk * 66 + ypg * 4 + 2];
                u64 uv[4] = {u01.x, u01.y, u23.x, u23.y};
                u64 cp[4] = {pack2(c4.x, c4.x), pack2(c4.y, c4.y),
                             pack2(c4.z, c4.z), pack2(c4.w, c4.w)};
#pragma unroll
                for (int i = 0; i < 4; i++)
#pragma unroll
                    for (int j = 0; j < 4; j++)
                        acc[i][j] = ffma2(cp[i], uv[j], acc[i][j]);
            }
        }
    }

    // combine k-halves (lane ^ 16 holds partner partials)
#pragma unroll
    for (int i = 0; i < 4; i++)
#pragma unroll
        for (int j = 0; j < 4; j++) {
            u64 o = __shfl_xor_sync(0xffffffffu, acc[i][j], 16);
            acc[i][j] = fadd2(acc[i][j], o);
        }

    if (khalf == 0) {
        float bb8[8];
        float4 t0v = *(const float4*)(bias + ypg * 8);
        float4 t1v = *(const float4*)(bias + ypg * 8 + 4);
        bb8[0]=t0v.x; bb8[1]=t0v.y; bb8[2]=t0v.z; bb8[3]=t0v.w;
        bb8[4]=t1v.x; bb8[5]=t1v.y; bb8[6]=t1v.z; bb8[7]=t1v.w;
#pragma unroll
        for (int i = 0; i < 4; i++) {
            int b = b0 + bg * 4 + i;
            float2 v0 = unpack2(acc[i][0]);
            float2 v1 = unpack2(acc[i][1]);
            float2 v2 = unpack2(acc[i][2]);
            float2 v3 = unpack2(acc[i][3]);
            float4 o0 = make_float4(v0.x + bb8[0], v0.y + bb8[1],
                                    v1.x + bb8[2], v1.y + bb8[3]);
            float4 o1 = make_float4(v2.x + bb8[4], v2.y + bb8[5],
                                    v3.x + bb8[6], v3.y + bb8[7]);
            *(float4*)&out[b * 128 + ypg * 8] = o0;
            *(float4*)&out[b * 128 + ypg * 8 + 4] = o1;
        }
    }
}

extern "C" void kernel_launch(void* const* d_in, const int* in_sizes, int n_in,
                              void* d_out, int out_size) {
    const float* LT = (const float*)d_in[0];
    const float* K  = (const float*)d_in[1];
    const float* AT = (const float*)d_in[2];
    const float* u  = (const float*)d_in[3];
    const float* e  = (const float*)d_in[4];
    const float* bv = (const float*)d_in[5];
    const int* ms   = (const int*)d_in[6];

    cudaFuncSetAttribute(iter_chunk, cudaFuncAttributeMaxDynamicSharedMemorySize,
                         SHBYTES);

    init_kernel<<<1, 64>>>();
    for (int t0 = 0; t0 < NSTEP; t0 += CHUNK)
        iter_chunk<<<128, 512, SHBYTES>>>(LT, K, AT, ms, t0);
    out_kernel<<<128, 256>>>(K, u, e, bv, ms, (float*)d_out);
}